// round 4
// baseline (speedup 1.0000x reference)
#include <cuda_runtime.h>
#include <cuda_fp16.h>
#include <cstdint>

// ============================================================================
// y[16384,4096] = x[16384,4096] @ W^T + bias, clamp to +-65176.48
// HARNESS DTYPES: fp16 arrays are cast to float32. So:
//   d_in[0] x     : float32 (8*2048*4096)
//   d_in[1] qweight: int32   (4,4096,128)  MSB-first bitplanes
//   d_in[2] lut   : float32 (4096,16)
//   d_in[3] bias  : float32 (4096)
//   d_out  y      : float32 (16384,4096)
// Family-baseline ISA only (sm_103, no 'a'): cp.async + ldmatrix + mma.sync.
// ============================================================================

#define O_DIM 4096
#define I_DIM 4096
#define M_TOTAL 16384

#define BM 128
#define BN 256
#define BK 32
#define STAGES 4
#define ITERS (I_DIM / BK)           // 128
#define THREADS 256                  // 8 warps: 2(m) x 4(n), warp tile 64x64

#define ROW_BYTES 80                 // (BK+8) halfs -> conflict-free ldmatrix
#define A_STAGE_BYTES (BM * ROW_BYTES)         // 10240
#define B_STAGE_BYTES (BN * ROW_BYTES)         // 20480
#define STAGE_BYTES (A_STAGE_BYTES + B_STAGE_BYTES)   // 30720
#define SMEM_BYTES (STAGES * STAGE_BYTES)      // 122880

#define N_TILES (O_DIM / BN)           // 16
#define M_TILES (M_TOTAL / BM)         // 128
#define GRID_CTAS (N_TILES * M_TILES)  // 2048

static constexpr float CLAMP_V = 65176.48f;  // finfo(fp16).max * 0.995

// Scratch: dequantized weight (O,I) fp16 and x converted to fp16.
__device__ __align__(1024) __half g_weight[(size_t)O_DIM * I_DIM];
__device__ __align__(1024) __half g_x[(size_t)M_TOTAL * I_DIM];

// ============================================================================
// helpers (sm_80-level PTX only)
// ============================================================================
__device__ __forceinline__ uint32_t smem_u32(const void* p) {
    uint32_t a;
    asm("{ .reg .u64 t; cvta.to.shared.u64 t, %1; cvt.u32.u64 %0, t; }"
        : "=r"(a) : "l"(p));
    return a;
}

__device__ __forceinline__ void cp_async16(uint32_t dst, const void* src) {
    asm volatile("cp.async.cg.shared.global [%0], [%1], 16;"
                 :: "r"(dst), "l"(src));
}
__device__ __forceinline__ void cp_commit() {
    asm volatile("cp.async.commit_group;");
}
template <int N>
__device__ __forceinline__ void cp_wait_group() {
    asm volatile("cp.async.wait_group %0;" :: "n"(N));
}

__device__ __forceinline__ void ldmatrix_x4(uint32_t* r, uint32_t addr) {
    asm volatile("ldmatrix.sync.aligned.m8n8.x4.shared.b16 {%0,%1,%2,%3}, [%4];"
                 : "=r"(r[0]), "=r"(r[1]), "=r"(r[2]), "=r"(r[3]) : "r"(addr));
}

__device__ __forceinline__ void mma16816(float* c, const uint32_t* a,
                                         uint32_t b0, uint32_t b1) {
    asm volatile(
        "mma.sync.aligned.m16n8k16.row.col.f32.f16.f16.f32 "
        "{%0,%1,%2,%3}, {%4,%5,%6,%7}, {%8,%9}, {%0,%1,%2,%3};"
        : "+f"(c[0]), "+f"(c[1]), "+f"(c[2]), "+f"(c[3])
        : "r"(a[0]), "r"(a[1]), "r"(a[2]), "r"(a[3]), "r"(b0), "r"(b1));
}

// ============================================================================
// Kernel 0: float32 x -> fp16 g_x  (vectorized 8 elems/thread)
// ============================================================================
__global__ void __launch_bounds__(256) convert_x_kernel(const float* __restrict__ x) {
    const size_t i = ((size_t)blockIdx.x * 256 + threadIdx.x) * 8;
    const float4 v0 = *reinterpret_cast<const float4*>(x + i);
    const float4 v1 = *reinterpret_cast<const float4*>(x + i + 4);
    __half2 h[4];
    h[0] = __floats2half2_rn(v0.x, v0.y);
    h[1] = __floats2half2_rn(v0.z, v0.w);
    h[2] = __floats2half2_rn(v1.x, v1.y);
    h[3] = __floats2half2_rn(v1.z, v1.w);
    *reinterpret_cast<uint4*>(g_x + i) = *reinterpret_cast<const uint4*>(h);
}

// ============================================================================
// Kernel 1: bitplane LUT dequant -> g_weight (O, I) fp16
//   1 warp per output row; lanes 0-15 cache lut[o] (as fp16 bits); shfl = LUT.
// ============================================================================
__global__ void __launch_bounds__(256) dequant_kernel(
    const int* __restrict__ qw, const float* __restrict__ lut) {
    const int lane = threadIdx.x & 31;
    const int o = blockIdx.x * 8 + (threadIdx.x >> 5);   // 512 blocks x 8 warps

    const uint32_t lv =
        (uint32_t)__half_as_ushort(__float2half_rn(lut[o * 16 + (lane & 15)]));

    const int* q0 = qw + 0 * O_DIM * 128 + o * 128;
    const int* q1 = qw + 1 * O_DIM * 128 + o * 128;
    const int* q2 = qw + 2 * O_DIM * 128 + o * 128;
    const int* q3 = qw + 3 * O_DIM * 128 + o * 128;
    __half* wrow = g_weight + (size_t)o * I_DIM;

    #pragma unroll
    for (int it = 0; it < 4; it++) {
        const int g = it * 32 + lane;
        const uint32_t p0 = (uint32_t)q0[g];   // MSB plane
        const uint32_t p1 = (uint32_t)q1[g];
        const uint32_t p2 = (uint32_t)q2[g];
        const uint32_t p3 = (uint32_t)q3[g];   // LSB plane
        uint32_t packed[16];
        #pragma unroll
        for (int i = 0; i < 32; i += 2) {
            uint32_t c0 = (((p0 >> i) & 1u) << 3) | (((p1 >> i) & 1u) << 2) |
                          (((p2 >> i) & 1u) << 1) | ((p3 >> i) & 1u);
            uint32_t c1 = (((p0 >> (i + 1)) & 1u) << 3) | (((p1 >> (i + 1)) & 1u) << 2) |
                          (((p2 >> (i + 1)) & 1u) << 1) | ((p3 >> (i + 1)) & 1u);
            uint32_t w0 = __shfl_sync(0xFFFFFFFFu, lv, (int)c0);
            uint32_t w1 = __shfl_sync(0xFFFFFFFFu, lv, (int)c1);
            packed[i >> 1] = (w0 & 0xFFFFu) | (w1 << 16);
        }
        uint4* dst = reinterpret_cast<uint4*>(wrow + g * 32);
        dst[0] = make_uint4(packed[0],  packed[1],  packed[2],  packed[3]);
        dst[1] = make_uint4(packed[4],  packed[5],  packed[6],  packed[7]);
        dst[2] = make_uint4(packed[8],  packed[9],  packed[10], packed[11]);
        dst[3] = make_uint4(packed[12], packed[13], packed[14], packed[15]);
    }
}

// ============================================================================
// Kernel 2: pipelined HMMA GEMM. CTA tile 128x256, 4-stage cp.async.
// ============================================================================
__global__ void __launch_bounds__(THREADS, 1) gemm_kernel(
    const float* __restrict__ bias, float* __restrict__ out) {
    extern __shared__ __align__(128) char smem[];
    const uint32_t sbase = smem_u32(smem);

    const int tid = threadIdx.x;
    const int lane = tid & 31;
    const int warp = tid >> 5;
    const int wm = warp >> 2;            // 0..1
    const int wn = warp & 3;             // 0..3

    // block swizzle: 8 consecutive m-tiles x 16 n-tiles per super-row
    const int bx = blockIdx.x;
    const int n_tile = bx & (N_TILES - 1);
    const int m_tile = ((bx >> 7) << 3) | ((bx >> 4) & 7);
    const int mBase = m_tile * BM;
    const int nBase = n_tile * BN;

    const __half* gA = g_x + (size_t)mBase * I_DIM;
    const __half* gW = g_weight + (size_t)nBase * I_DIM;

    float acc[4][8][4];
    #pragma unroll
    for (int i = 0; i < 4; i++)
        #pragma unroll
        for (int j = 0; j < 8; j++)
            #pragma unroll
            for (int q = 0; q < 4; q++) acc[i][j][q] = 0.0f;

    const int arow0 = tid >> 2, aseg = (tid & 3);

    const uint32_t a_lane =
        (uint32_t)((wm * 64 + (lane & 15)) * ROW_BYTES + (lane >> 4) * 16);
    const uint32_t b_lane =
        (uint32_t)((wn * 64 + (lane & 7) + ((lane >> 4) << 3)) * ROW_BYTES +
                   ((lane >> 3) & 1) * 16);

#define LOAD_STAGE(stage, kc) do {                                            \
        const uint32_t s_a = sbase + (uint32_t)(stage) * STAGE_BYTES;         \
        const uint32_t s_b = s_a + A_STAGE_BYTES;                             \
        const int kofs = (kc) * BK;                                           \
        _Pragma("unroll")                                                     \
        for (int p = 0; p < 2; p++) {                                         \
            int row = arow0 + p * 64;                                         \
            cp_async16(s_a + row * ROW_BYTES + aseg * 16,                     \
                       gA + (size_t)row * I_DIM + kofs + aseg * 8);           \
        }                                                                     \
        _Pragma("unroll")                                                     \
        for (int p = 0; p < 4; p++) {                                         \
            int row = arow0 + p * 64;                                         \
            cp_async16(s_b + row * ROW_BYTES + aseg * 16,                     \
                       gW + (size_t)row * I_DIM + kofs + aseg * 8);           \
        }                                                                     \
    } while (0)

    #pragma unroll
    for (int s = 0; s < STAGES - 1; s++) {
        LOAD_STAGE(s, s);
        cp_commit();
    }

    int kn = STAGES - 1;
    #pragma unroll 1
    for (int it = 0; it < ITERS; it++) {
        cp_wait_group<STAGES - 2>();
        __syncthreads();

        if (kn < ITERS) LOAD_STAGE(kn & (STAGES - 1), kn);
        cp_commit();
        kn++;

        const uint32_t s_a = sbase + (uint32_t)(it & (STAGES - 1)) * STAGE_BYTES;
        const uint32_t s_b = s_a + A_STAGE_BYTES;

        #pragma unroll
        for (int s = 0; s < 2; s++) {          // two k=16 steps
            const uint32_t ka = s * 32;
            uint32_t a_regs[4][4];
            #pragma unroll
            for (int i = 0; i < 4; i++)
                ldmatrix_x4(a_regs[i], s_a + a_lane + i * 16 * ROW_BYTES + ka);
            uint32_t b_regs[4][4];
            #pragma unroll
            for (int jj = 0; jj < 4; jj++)
                ldmatrix_x4(b_regs[jj], s_b + b_lane + jj * 16 * ROW_BYTES + ka);
            #pragma unroll
            for (int i = 0; i < 4; i++)
                #pragma unroll
                for (int j = 0; j < 8; j++)
                    mma16816(acc[i][j], a_regs[i],
                             b_regs[j >> 1][(j & 1) * 2],
                             b_regs[j >> 1][(j & 1) * 2 + 1]);
        }
    }

    // ---------------- epilogue: bias + clamp + float32 store ----------------
    float2 fb[8];
    #pragma unroll
    for (int j = 0; j < 8; j++) {
        const int col = nBase + wn * 64 + j * 8 + (lane & 3) * 2;
        fb[j] = *reinterpret_cast<const float2*>(bias + col);
    }

    #pragma unroll
    for (int i = 0; i < 4; i++) {
        const int row0 = mBase + wm * 64 + i * 16 + (lane >> 2);
        #pragma unroll
        for (int rr = 0; rr < 2; rr++) {
            const size_t row = (size_t)(row0 + rr * 8);
            float* orow = out + row * O_DIM + nBase + wn * 64 + (lane & 3) * 2;
            #pragma unroll
            for (int j = 0; j < 8; j++) {
                float v0 = acc[i][j][rr * 2 + 0] + fb[j].x;
                float v1 = acc[i][j][rr * 2 + 1] + fb[j].y;
                v0 = fminf(fmaxf(v0, -CLAMP_V), CLAMP_V);
                v1 = fminf(fmaxf(v1, -CLAMP_V), CLAMP_V);
                *reinterpret_cast<float2*>(orow + j * 8) = make_float2(v0, v1);
            }
        }
    }
#undef LOAD_STAGE
}

// ============================================================================
// Host launcher
// ============================================================================
extern "C" void kernel_launch(void* const* d_in, const int* in_sizes, int n_in,
                              void* d_out, int out_size) {
    (void)in_sizes; (void)n_in; (void)out_size;
    const float* x    = (const float*)d_in[0];
    const int*   qw   = (const int*)d_in[1];
    const float* lut  = (const float*)d_in[2];
    const float* bias = (const float*)d_in[3];
    float* out = (float*)d_out;

    convert_x_kernel<<<(M_TOTAL * (size_t)I_DIM) / (256 * 8), 256>>>(x);
    dequant_kernel<<<512, 256>>>(qw, lut);

    cudaFuncSetAttribute(gemm_kernel, cudaFuncAttributeMaxDynamicSharedMemorySize,
                         SMEM_BYTES);
    gemm_kernel<<<GRID_CTAS, THREADS, SMEM_BYTES>>>(bias, out);
}

// round 5
// speedup vs baseline: 1.2582x; 1.2582x over previous
#include <cuda_runtime.h>
#include <cuda_fp16.h>
#include <cstdint>

// ============================================================================
// y[16384,4096] = x[16384,4096] @ W^T + bias, clamp to +-65176.48
// Harness dtypes: fp16 tensors arrive as float32.
//   d_in[0] x: f32 (16384,4096)   d_in[1] qweight: i32 (4,4096,128)
//   d_in[2] lut: f32 (4096,16)    d_in[3] bias: f32 (4096)
//   d_out y: f32 (16384,4096)
// Family-baseline ISA only (sm_103): cp.async + ldmatrix + mma.sync.
// ============================================================================

#define O_DIM 4096
#define I_DIM 4096
#define M_TOTAL 16384

#define BM 128
#define BN 256
#define BK 64
#define STAGES 3
#define ITERS (I_DIM / BK)           // 64
#define THREADS 256                  // 8 warps: 2(m) x 4(n), warp tile 64x64

#define ROW_BYTES 128                // BK halfs, XOR-swizzled (no padding)
#define A_STAGE_BYTES (BM * ROW_BYTES)                // 16384
#define B_STAGE_BYTES (BN * ROW_BYTES)                // 32768
#define STAGE_BYTES (A_STAGE_BYTES + B_STAGE_BYTES)   // 49152
#define SMEM_BYTES (STAGES * STAGE_BYTES)             // 147456

#define N_TILES (O_DIM / BN)           // 16
#define M_TILES (M_TOTAL / BM)         // 128
#define GRID_CTAS (N_TILES * M_TILES)  // 2048

#define DQ_BLOCKS 512                  // dequant part of prep kernel
#define CVT_BLOCKS ((M_TOTAL * I_DIM) / (256 * 8))   // 32768
#define PREP_BLOCKS (DQ_BLOCKS + CVT_BLOCKS)

static constexpr float CLAMP_V = 65176.48f;  // finfo(fp16).max * 0.995

// Scratch: dequantized weight (O,I) fp16 and x converted to fp16.
__device__ __align__(1024) __half g_weight[(size_t)O_DIM * I_DIM];
__device__ __align__(1024) __half g_x[(size_t)M_TOTAL * I_DIM];

// ============================================================================
// helpers (sm_80-level PTX only)
// ============================================================================
__device__ __forceinline__ uint32_t smem_u32(const void* p) {
    uint32_t a;
    asm("{ .reg .u64 t; cvta.to.shared.u64 t, %1; cvt.u32.u64 %0, t; }"
        : "=r"(a) : "l"(p));
    return a;
}

__device__ __forceinline__ void cp_async16(uint32_t dst, const void* src) {
    asm volatile("cp.async.cg.shared.global [%0], [%1], 16;"
                 :: "r"(dst), "l"(src));
}
__device__ __forceinline__ void cp_commit() {
    asm volatile("cp.async.commit_group;");
}
template <int N>
__device__ __forceinline__ void cp_wait_group() {
    asm volatile("cp.async.wait_group %0;" :: "n"(N));
}

__device__ __forceinline__ void ldmatrix_x4(uint32_t* r, uint32_t addr) {
    asm volatile("ldmatrix.sync.aligned.m8n8.x4.shared.b16 {%0,%1,%2,%3}, [%4];"
                 : "=r"(r[0]), "=r"(r[1]), "=r"(r[2]), "=r"(r[3]) : "r"(addr));
}

__device__ __forceinline__ void mma16816(float* c, const uint32_t* a,
                                         uint32_t b0, uint32_t b1) {
    asm volatile(
        "mma.sync.aligned.m16n8k16.row.col.f32.f16.f16.f32 "
        "{%0,%1,%2,%3}, {%4,%5,%6,%7}, {%8,%9}, {%0,%1,%2,%3};"
        : "+f"(c[0]), "+f"(c[1]), "+f"(c[2]), "+f"(c[3])
        : "r"(a[0]), "r"(a[1]), "r"(a[2]), "r"(a[3]), "r"(b0), "r"(b1));
}

// ============================================================================
// Kernel 1 (prep): blocks [0,512) dequant bitplanes; rest convert x -> fp16
// ============================================================================
__global__ void __launch_bounds__(256) prep_kernel(
    const int* __restrict__ qw, const float* __restrict__ lut,
    const float* __restrict__ x) {
    if (blockIdx.x < DQ_BLOCKS) {
        // ---- dequant: 1 warp per output row; shfl.idx as 16-entry LUT ----
        const int lane = threadIdx.x & 31;
        const int o = blockIdx.x * 8 + (threadIdx.x >> 5);

        const uint32_t lv =
            (uint32_t)__half_as_ushort(__float2half_rn(lut[o * 16 + (lane & 15)]));

        const int* q0 = qw + 0 * O_DIM * 128 + o * 128;
        const int* q1 = qw + 1 * O_DIM * 128 + o * 128;
        const int* q2 = qw + 2 * O_DIM * 128 + o * 128;
        const int* q3 = qw + 3 * O_DIM * 128 + o * 128;
        __half* wrow = g_weight + (size_t)o * I_DIM;

        #pragma unroll
        for (int it = 0; it < 4; it++) {
            const int g = it * 32 + lane;
            const uint32_t p0 = (uint32_t)q0[g];   // MSB plane
            const uint32_t p1 = (uint32_t)q1[g];
            const uint32_t p2 = (uint32_t)q2[g];
            const uint32_t p3 = (uint32_t)q3[g];   // LSB plane
            uint32_t packed[16];
            #pragma unroll
            for (int i = 0; i < 32; i += 2) {
                uint32_t c0 = (((p0 >> i) & 1u) << 3) | (((p1 >> i) & 1u) << 2) |
                              (((p2 >> i) & 1u) << 1) | ((p3 >> i) & 1u);
                uint32_t c1 = (((p0 >> (i + 1)) & 1u) << 3) |
                              (((p1 >> (i + 1)) & 1u) << 2) |
                              (((p2 >> (i + 1)) & 1u) << 1) |
                              ((p3 >> (i + 1)) & 1u);
                uint32_t w0 = __shfl_sync(0xFFFFFFFFu, lv, (int)c0);
                uint32_t w1 = __shfl_sync(0xFFFFFFFFu, lv, (int)c1);
                packed[i >> 1] = (w0 & 0xFFFFu) | (w1 << 16);
            }
            uint4* dst = reinterpret_cast<uint4*>(wrow + g * 32);
            dst[0] = make_uint4(packed[0],  packed[1],  packed[2],  packed[3]);
            dst[1] = make_uint4(packed[4],  packed[5],  packed[6],  packed[7]);
            dst[2] = make_uint4(packed[8],  packed[9],  packed[10], packed[11]);
            dst[3] = make_uint4(packed[12], packed[13], packed[14], packed[15]);
        }
    } else {
        // ---- convert: f32 -> fp16, 8 elems/thread ----
        const size_t i =
            ((size_t)(blockIdx.x - DQ_BLOCKS) * 256 + threadIdx.x) * 8;
        const float4 v0 = *reinterpret_cast<const float4*>(x + i);
        const float4 v1 = *reinterpret_cast<const float4*>(x + i + 4);
        __half2 h[4];
        h[0] = __floats2half2_rn(v0.x, v0.y);
        h[1] = __floats2half2_rn(v0.z, v0.w);
        h[2] = __floats2half2_rn(v1.x, v1.y);
        h[3] = __floats2half2_rn(v1.z, v1.w);
        *reinterpret_cast<uint4*>(g_x + i) = *reinterpret_cast<const uint4*>(h);
    }
}

// ============================================================================
// Kernel 2: pipelined HMMA GEMM. CTA 128x256, BK=64, 3-stage cp.async,
// XOR-swizzled smem (128B rows), double-buffered ldmatrix fragments.
// ============================================================================
__global__ void __launch_bounds__(THREADS, 1) gemm_kernel(
    const float* __restrict__ bias, float* __restrict__ out) {
    extern __shared__ __align__(1024) char smem[];
    const uint32_t sbase = smem_u32(smem);

    const int tid = threadIdx.x;
    const int lane = tid & 31;
    const int warp = tid >> 5;
    const int wm = warp >> 2;            // 0..1
    const int wn = warp & 3;             // 0..3

    // block swizzle: 8 consecutive m-tiles x 16 n-tiles per super-row
    const int bx = blockIdx.x;
    const int n_tile = bx & (N_TILES - 1);
    const int m_tile = ((bx >> 7) << 3) | ((bx >> 4) & 7);
    const int mBase = m_tile * BM;
    const int nBase = n_tile * BN;

    const __half* gA = g_x + (size_t)mBase * I_DIM;
    const __half* gW = g_weight + (size_t)nBase * I_DIM;

    float acc[4][8][4];
    #pragma unroll
    for (int i = 0; i < 4; i++)
        #pragma unroll
        for (int j = 0; j < 8; j++)
            #pragma unroll
            for (int q = 0; q < 4; q++) acc[i][j][q] = 0.0f;

    // ---- cp.async coords: chunk id -> (row, xor-swizzled 16B unit) ----
    // A: 128 rows x 8 units = 1024 chunks (4/thread); B: 2048 (8/thread)
    // smem addr = row*128 + (unit ^ (row&7))*16 ; gmem = row*I_DIM + k + unit*8

    // ---- ldmatrix per-lane constants ----
    const uint32_t rxor = (uint32_t)(lane & 7);          // row&7 for both A,B
    uint32_t a_row_off[4], b_row_off[4];
    #pragma unroll
    for (int i = 0; i < 4; i++)
        a_row_off[i] = (uint32_t)((wm * 64 + i * 16 + (lane & 15)) * ROW_BYTES);
    #pragma unroll
    for (int jj = 0; jj < 4; jj++)
        b_row_off[jj] = (uint32_t)((wn * 64 + jj * 16 + (lane & 7) +
                                    ((lane >> 4) << 3)) * ROW_BYTES);
    const uint32_t a_ku = (uint32_t)(lane >> 4);         // 0/1 : +8 halfs in k
    const uint32_t b_ku = (uint32_t)((lane >> 3) & 1);

#define LOAD_STAGE(stage, kc) do {                                            \
        const uint32_t s_a = sbase + (uint32_t)(stage) * STAGE_BYTES;         \
        const uint32_t s_b = s_a + A_STAGE_BYTES;                             \
        const int kofs = (kc) * BK;                                           \
        _Pragma("unroll")                                                     \
        for (int t = 0; t < 4; t++) {                                         \
            const int id = tid + t * 256;                                     \
            const int row = id >> 3, unit = id & 7;                           \
            cp_async16(s_a + row * ROW_BYTES + ((unit ^ (row & 7)) << 4),     \
                       gA + (size_t)row * I_DIM + kofs + unit * 8);           \
        }                                                                     \
        _Pragma("unroll")                                                     \
        for (int t = 0; t < 8; t++) {                                         \
            const int id = tid + t * 256;                                     \
            const int row = id >> 3, unit = id & 7;                           \
            cp_async16(s_b + row * ROW_BYTES + ((unit ^ (row & 7)) << 4),     \
                       gW + (size_t)row * I_DIM + kofs + unit * 8);           \
        }                                                                     \
    } while (0)

#define LOAD_FRAGS(buf, s_a, s_b, sk) do {                                    \
        const uint32_t au = (((uint32_t)(sk) * 2 + a_ku) ^ rxor) << 4;        \
        const uint32_t bu = (((uint32_t)(sk) * 2 + b_ku) ^ rxor) << 4;        \
        _Pragma("unroll")                                                     \
        for (int i = 0; i < 4; i++)                                           \
            ldmatrix_x4(a_regs[buf][i], (s_a) + a_row_off[i] + au);           \
        _Pragma("unroll")                                                     \
        for (int jj = 0; jj < 4; jj++)                                        \
            ldmatrix_x4(b_regs[buf][jj], (s_b) + b_row_off[jj] + bu);         \
    } while (0)

    // prologue: 2 stages in flight
    #pragma unroll
    for (int s = 0; s < STAGES - 1; s++) {
        LOAD_STAGE(s, s);
        cp_commit();
    }

    uint32_t a_regs[2][4][4], b_regs[2][4][4];

    int kn = STAGES - 1;
    int stage = 0;
    #pragma unroll 1
    for (int it = 0; it < ITERS; it++) {
        cp_wait_group<STAGES - 2>();
        __syncthreads();

        if (kn < ITERS) {
            LOAD_STAGE(kn == ITERS ? 0 : (kn % STAGES), kn);
        }
        cp_commit();
        kn++;

        const uint32_t s_a = sbase + (uint32_t)stage * STAGE_BYTES;
        const uint32_t s_b = s_a + A_STAGE_BYTES;
        if (++stage == STAGES) stage = 0;

        LOAD_FRAGS(0, s_a, s_b, 0);
        #pragma unroll
        for (int sk = 0; sk < 4; sk++) {       // 4 k=16 steps
            const int cur = sk & 1;
            if (sk < 3) LOAD_FRAGS(cur ^ 1, s_a, s_b, sk + 1);
            #pragma unroll
            for (int i = 0; i < 4; i++)
                #pragma unroll
                for (int j = 0; j < 8; j++)
                    mma16816(acc[i][j], a_regs[cur][i],
                             b_regs[cur][j >> 1][(j & 1) * 2],
                             b_regs[cur][j >> 1][(j & 1) * 2 + 1]);
        }
        __syncthreads();   // all frags consumed before producer overwrites
    }

    // ---------------- epilogue: bias + clamp + float32 store ----------------
    float2 fb[8];
    #pragma unroll
    for (int j = 0; j < 8; j++) {
        const int col = nBase + wn * 64 + j * 8 + (lane & 3) * 2;
        fb[j] = *reinterpret_cast<const float2*>(bias + col);
    }

    #pragma unroll
    for (int i = 0; i < 4; i++) {
        const int row0 = mBase + wm * 64 + i * 16 + (lane >> 2);
        #pragma unroll
        for (int rr = 0; rr < 2; rr++) {
            const size_t row = (size_t)(row0 + rr * 8);
            float* orow = out + row * O_DIM + nBase + wn * 64 + (lane & 3) * 2;
            #pragma unroll
            for (int j = 0; j < 8; j++) {
                float v0 = acc[i][j][rr * 2 + 0] + fb[j].x;
                float v1 = acc[i][j][rr * 2 + 1] + fb[j].y;
                v0 = fminf(fmaxf(v0, -CLAMP_V), CLAMP_V);
                v1 = fminf(fmaxf(v1, -CLAMP_V), CLAMP_V);
                *reinterpret_cast<float2*>(orow + j * 8) = make_float2(v0, v1);
            }
        }
    }
#undef LOAD_STAGE
#undef LOAD_FRAGS
}

// ============================================================================
// Host launcher
// ============================================================================
extern "C" void kernel_launch(void* const* d_in, const int* in_sizes, int n_in,
                              void* d_out, int out_size) {
    (void)in_sizes; (void)n_in; (void)out_size;
    const float* x    = (const float*)d_in[0];
    const int*   qw   = (const int*)d_in[1];
    const float* lut  = (const float*)d_in[2];
    const float* bias = (const float*)d_in[3];
    float* out = (float*)d_out;

    prep_kernel<<<PREP_BLOCKS, 256>>>(qw, lut, x);

    cudaFuncSetAttribute(gemm_kernel, cudaFuncAttributeMaxDynamicSharedMemorySize,
                         SMEM_BYTES);
    gemm_kernel<<<GRID_CTAS, THREADS, SMEM_BYTES>>>(bias, out);
}